// round 1
// baseline (speedup 1.0000x reference)
#include <cuda_runtime.h>
#include <cuda_bf16.h>
#include <stdint.h>

typedef __nv_bfloat16 bf16;

#define NB 8
#define NT 2048
#define NC 512
#define NX (NB*NT*NC)          // 8388608 elements per (B,T,C) tensor
#define NW (NC*NC)             // 262144

// ---------------- scratch (static device globals; no runtime allocation) ----
__device__ bf16 g_xbl[NX];
__device__ bf16 g_xbr[NX];
__device__ bf16 g_wts[6*NW];           // lp1_w1, rp1_w1, lp2_w1, rp2_w1, lp3_w, rp3_w (bf16)
__device__ bf16 g_H[NX];               // pointwise output, reused per projection
__device__ bf16 g_Ql[NX];
__device__ bf16 g_Qr[NX];
__device__ bf16 g_Vt[NX];              // depthwise output pre-transpose
__device__ bf16 g_VlT[NX];             // (b, c, t)
__device__ bf16 g_VrT[NX];             // (b, c, t)
__device__ bf16 g_E [33554432];        // exp(scores), (b, t, s)
__device__ bf16 g_ET[33554432];        // transposed,  (b, s, t)
__device__ bf16 g_F1[NX];              // F_r2l (b,t,c)
__device__ bf16 g_F2[NX];              // F_l2r (b,s,c)
__device__ float g_rinv[NB*NT];
__device__ float g_cinv[NB*NT];

// ---------------- helpers ---------------------------------------------------
__device__ __forceinline__ float fexp_(float x){
    // values here are ~|x| < 0.01; Taylor avoids MUFU bottleneck. Fallback is exact-ish.
    if (fabsf(x) < 0.25f){
        return 1.f + x*(1.f + x*(0.5f + x*(0.16666667f + x*0.04166667f)));
    }
    return __expf(x);
}

// ---------------- fp32 -> bf16 convert --------------------------------------
__global__ void k_f2bf(const float* __restrict__ in, bf16* __restrict__ out, int n){
    int i = (blockIdx.x * 256 + threadIdx.x) * 4;
    if (i + 3 < n){
        float4 v = *(const float4*)(in + i);
        *(__nv_bfloat162*)(out + i    ) = __floats2bfloat162_rn(v.x, v.y);
        *(__nv_bfloat162*)(out + i + 2) = __floats2bfloat162_rn(v.z, v.w);
    }
}

// ---------------- depthwise conv k=3 over T, per-batch zero pad -------------
__global__ void k_dw(const bf16* __restrict__ H, const float* __restrict__ w2,
                     const float* __restrict__ b2, bf16* __restrict__ out){
    int i = blockIdx.x * 256 + threadIdx.x;      // one bf16 pair per thread
    const int CP = NC / 2;
    int cp = i % CP;
    int t  = (i / CP) % NT;
    int b  = i / (CP * NT);
    int c  = cp * 2;
    size_t base = ((size_t)b * NT + t) * NC + c;
    float2 h0 = __bfloat1622float2(*(const __nv_bfloat162*)(H + base));
    float2 hm = make_float2(0.f, 0.f), hp = make_float2(0.f, 0.f);
    if (t > 0)      hm = __bfloat1622float2(*(const __nv_bfloat162*)(H + base - NC));
    if (t < NT - 1) hp = __bfloat1622float2(*(const __nv_bfloat162*)(H + base + NC));
    float o0 = hm.x * w2[c*3+0] + h0.x * w2[c*3+1] + hp.x * w2[c*3+2] + b2[c];
    float o1 = hm.y * w2[c*3+3] + h0.y * w2[c*3+4] + hp.y * w2[c*3+5] + b2[c+1];
    *(__nv_bfloat162*)(out + base) = __floats2bfloat162_rn(o0, o1);
}

// ---------------- tiled bf16 transpose: (z,R,C) -> (z,C,R) ------------------
__global__ void k_transpose(const bf16* __restrict__ in, bf16* __restrict__ out,
                            int R, int Cd){
    __shared__ bf16 ts[64][66];
    size_t base = (size_t)blockIdx.z * R * Cd;
    int r0 = blockIdx.y * 64, c0 = blockIdx.x * 64;
    #pragma unroll
    for (int it = 0; it < 2; it++){
        int q  = threadIdx.x + it * 256;         // 0..511 chunks of 8
        int r  = q >> 3, c8 = (q & 7) * 8;
        uint4 v = *(const uint4*)(in + base + (size_t)(r0 + r) * Cd + c0 + c8);
        uint32_t* s = (uint32_t*)&ts[r][c8];
        s[0] = v.x; s[1] = v.y; s[2] = v.z; s[3] = v.w;
    }
    __syncthreads();
    #pragma unroll
    for (int it = 0; it < 8; it++){
        int p = threadIdx.x + it * 256;          // 0..2047
        int c = p >> 5, r = (p & 31) * 2;
        __nv_bfloat162 v;
        v.x = ts[r][c]; v.y = ts[r + 1][c];
        *(__nv_bfloat162*)(out + base + (size_t)(c0 + c) * R + r0 + r) = v;
    }
}

// ---------------- row sum -> reciprocal -------------------------------------
__global__ void k_rowsum_inv(const bf16* __restrict__ E, float* __restrict__ inv, int L){
    size_t row = blockIdx.x;
    const __nv_bfloat162* p = (const __nv_bfloat162*)(E + row * (size_t)L);
    float s = 0.f;
    for (int i = threadIdx.x; i < L / 2; i += 256){
        float2 f = __bfloat1622float2(p[i]);
        s += f.x + f.y;
    }
    #pragma unroll
    for (int off = 16; off; off >>= 1) s += __shfl_xor_sync(0xffffffffu, s, off);
    __shared__ float sh[8];
    if ((threadIdx.x & 31) == 0) sh[threadIdx.x >> 5] = s;
    __syncthreads();
    if (threadIdx.x == 0){
        float t = 0.f;
        #pragma unroll
        for (int i = 0; i < 8; i++) t += sh[i];
        inv[row] = 1.0f / t;
    }
}

// ---------------- NT bf16 GEMM: C[m,n] = epi( sum_k A[m,k] * B[n,k] ) -------
// EPI: 1 = +bias -> bf16 ; 2 = exp(alpha*acc) -> bf16 ;
//      3 = acc * rowscale[m] -> bf16 ; 4 = +bias + fp32 residual -> fp32
template<int EPI>
__global__ void __launch_bounds__(256, 2)
k_gemm_nt(const bf16* __restrict__ Ag, const bf16* __restrict__ Bg,
          void* __restrict__ Cg, int M, int N, int K,
          long long sA, long long sB, long long sC,
          const float* __restrict__ bias,
          const float* __restrict__ rowscale, int sRS,
          const float* __restrict__ resid, float alpha)
{
    __shared__ bf16 As[2][128][40];
    __shared__ bf16 Bs[2][128][40];
    const int tid = threadIdx.x;
    const int bz  = blockIdx.z;
    const bf16* A = Ag + (size_t)bz * sA;
    const bf16* B = Bg + (size_t)bz * sB;
    const int m0 = blockIdx.y * 128;
    const int n0 = blockIdx.x * 128;
    const int lrow = tid >> 2;
    const int lcol = (tid & 3) << 3;
    const int warp = tid >> 5, lane = tid & 31;
    const int wm = (warp & 1) << 6, wn = (warp >> 1) << 5;
    const int grp = lane >> 2, qid = lane & 3;

    float acc[4][4][4];
    #pragma unroll
    for (int i = 0; i < 4; i++)
        #pragma unroll
        for (int j = 0; j < 4; j++)
            #pragma unroll
            for (int k = 0; k < 4; k++) acc[i][j][k] = 0.f;

    const int nt = K >> 5;

    auto load_stage = [&](int kt, int buf){
        const int k0 = kt << 5;
        #pragma unroll
        for (int h = 0; h < 2; h++){
            int r = lrow + (h << 6);
            const bf16* ga = A + (size_t)(m0 + r) * K + k0 + lcol;
            uint32_t sa = (uint32_t)__cvta_generic_to_shared(&As[buf][r][lcol]);
            asm volatile("cp.async.cg.shared.global [%0], [%1], 16;\n" :: "r"(sa), "l"(ga));
            const bf16* gb = B + (size_t)(n0 + r) * K + k0 + lcol;
            uint32_t sb = (uint32_t)__cvta_generic_to_shared(&Bs[buf][r][lcol]);
            asm volatile("cp.async.cg.shared.global [%0], [%1], 16;\n" :: "r"(sb), "l"(gb));
        }
        asm volatile("cp.async.commit_group;\n");
    };

    load_stage(0, 0);
    for (int kt = 0; kt < nt; kt++){
        int buf = kt & 1;
        if (kt + 1 < nt){
            load_stage(kt + 1, buf ^ 1);
            asm volatile("cp.async.wait_group 1;\n");
        } else {
            asm volatile("cp.async.wait_group 0;\n");
        }
        __syncthreads();
        #pragma unroll
        for (int ks = 0; ks < 2; ks++){
            const int kk = ks << 4;
            uint32_t af[4][4], bfg[4][2];
            #pragma unroll
            for (int mi = 0; mi < 4; mi++){
                int r = wm + (mi << 4) + grp;
                af[mi][0] = *(const uint32_t*)&As[buf][r    ][kk + (qid << 1)];
                af[mi][1] = *(const uint32_t*)&As[buf][r + 8][kk + (qid << 1)];
                af[mi][2] = *(const uint32_t*)&As[buf][r    ][kk + (qid << 1) + 8];
                af[mi][3] = *(const uint32_t*)&As[buf][r + 8][kk + (qid << 1) + 8];
            }
            #pragma unroll
            for (int ni = 0; ni < 4; ni++){
                int r = wn + (ni << 3) + grp;
                bfg[ni][0] = *(const uint32_t*)&Bs[buf][r][kk + (qid << 1)];
                bfg[ni][1] = *(const uint32_t*)&Bs[buf][r][kk + (qid << 1) + 8];
            }
            #pragma unroll
            for (int mi = 0; mi < 4; mi++)
                #pragma unroll
                for (int ni = 0; ni < 4; ni++){
                    asm volatile(
                        "mma.sync.aligned.m16n8k16.row.col.f32.bf16.bf16.f32 "
                        "{%0,%1,%2,%3}, {%4,%5,%6,%7}, {%8,%9}, {%0,%1,%2,%3};\n"
                        : "+f"(acc[mi][ni][0]), "+f"(acc[mi][ni][1]),
                          "+f"(acc[mi][ni][2]), "+f"(acc[mi][ni][3])
                        : "r"(af[mi][0]), "r"(af[mi][1]), "r"(af[mi][2]), "r"(af[mi][3]),
                          "r"(bfg[ni][0]), "r"(bfg[ni][1]));
                }
        }
        __syncthreads();
    }

    #pragma unroll
    for (int mi = 0; mi < 4; mi++){
        #pragma unroll
        for (int ni = 0; ni < 4; ni++){
            int row = m0 + wm + (mi << 4) + grp;
            int col = n0 + wn + (ni << 3) + (qid << 1);
            float v0 = acc[mi][ni][0], v1 = acc[mi][ni][1];
            float v2 = acc[mi][ni][2], v3 = acc[mi][ni][3];
            if (EPI == 1){
                float b0 = bias[col], b1 = bias[col + 1];
                v0 += b0; v1 += b1; v2 += b0; v3 += b1;
            } else if (EPI == 2){
                v0 = fexp_(v0 * alpha); v1 = fexp_(v1 * alpha);
                v2 = fexp_(v2 * alpha); v3 = fexp_(v3 * alpha);
            } else if (EPI == 3){
                float r0 = rowscale[(size_t)bz * sRS + row];
                float r1 = rowscale[(size_t)bz * sRS + row + 8];
                v0 *= r0; v1 *= r0; v2 *= r1; v3 *= r1;
            } else if (EPI == 4){
                float b0 = bias[col], b1 = bias[col + 1];
                const float* R0 = resid + (size_t)row * N + col;
                const float* R1 = resid + (size_t)(row + 8) * N + col;
                v0 += b0 + R0[0]; v1 += b1 + R0[1];
                v2 += b0 + R1[0]; v3 += b1 + R1[1];
            }
            if (EPI == 4){
                float* C = (float*)Cg + (size_t)bz * sC;
                *(float2*)&C[(size_t)row * N + col]       = make_float2(v0, v1);
                *(float2*)&C[(size_t)(row + 8) * N + col] = make_float2(v2, v3);
            } else {
                bf16* C = (bf16*)Cg + (size_t)bz * sC;
                *(__nv_bfloat162*)&C[(size_t)row * N + col]       = __floats2bfloat162_rn(v0, v1);
                *(__nv_bfloat162*)&C[(size_t)(row + 8) * N + col] = __floats2bfloat162_rn(v2, v3);
            }
        }
    }
}

// ---------------- launcher --------------------------------------------------
extern "C" void kernel_launch(void* const* d_in, const int* in_sizes, int n_in,
                              void* d_out, int out_size){
    (void)in_sizes; (void)n_in; (void)out_size;
    const float* x_l    = (const float*)d_in[0];
    const float* x_r    = (const float*)d_in[1];
    const float* lp1_w1 = (const float*)d_in[2];
    const float* lp1_b1 = (const float*)d_in[3];
    const float* lp1_w2 = (const float*)d_in[4];
    const float* lp1_b2 = (const float*)d_in[5];
    const float* rp1_w1 = (const float*)d_in[6];
    const float* rp1_b1 = (const float*)d_in[7];
    const float* rp1_w2 = (const float*)d_in[8];
    const float* rp1_b2 = (const float*)d_in[9];
    const float* lp2_w1 = (const float*)d_in[10];
    const float* lp2_b1 = (const float*)d_in[11];
    const float* lp2_w2 = (const float*)d_in[12];
    const float* lp2_b2 = (const float*)d_in[13];
    const float* rp2_w1 = (const float*)d_in[14];
    const float* rp2_b1 = (const float*)d_in[15];
    const float* rp2_w2 = (const float*)d_in[16];
    const float* rp2_b2 = (const float*)d_in[17];
    const float* lp3_w  = (const float*)d_in[18];
    const float* lp3_b  = (const float*)d_in[19];
    const float* rp3_w  = (const float*)d_in[20];
    const float* rp3_b  = (const float*)d_in[21];

    bf16 *xbl, *xbr, *w, *H, *Ql, *Qr, *Vt, *VlT, *VrT, *E, *ET, *F1, *F2;
    float *rinv, *cinv;
    cudaGetSymbolAddress((void**)&xbl, g_xbl);
    cudaGetSymbolAddress((void**)&xbr, g_xbr);
    cudaGetSymbolAddress((void**)&w,   g_wts);
    cudaGetSymbolAddress((void**)&H,   g_H);
    cudaGetSymbolAddress((void**)&Ql,  g_Ql);
    cudaGetSymbolAddress((void**)&Qr,  g_Qr);
    cudaGetSymbolAddress((void**)&Vt,  g_Vt);
    cudaGetSymbolAddress((void**)&VlT, g_VlT);
    cudaGetSymbolAddress((void**)&VrT, g_VrT);
    cudaGetSymbolAddress((void**)&E,   g_E);
    cudaGetSymbolAddress((void**)&ET,  g_ET);
    cudaGetSymbolAddress((void**)&F1,  g_F1);
    cudaGetSymbolAddress((void**)&F2,  g_F2);
    cudaGetSymbolAddress((void**)&rinv, g_rinv);
    cudaGetSymbolAddress((void**)&cinv, g_cinv);

    const int nx = NX, nw = NW;
    const float scale = 0.04419417382415922f;   // 512^-0.5

    // convert inputs & weights to bf16
    k_f2bf<<<nx/1024, 256>>>(x_l, xbl, nx);
    k_f2bf<<<nx/1024, 256>>>(x_r, xbr, nx);
    k_f2bf<<<nw/1024, 256>>>(lp1_w1, w + 0*nw, nw);
    k_f2bf<<<nw/1024, 256>>>(rp1_w1, w + 1*nw, nw);
    k_f2bf<<<nw/1024, 256>>>(lp2_w1, w + 2*nw, nw);
    k_f2bf<<<nw/1024, 256>>>(rp2_w1, w + 3*nw, nw);
    k_f2bf<<<nw/1024, 256>>>(lp3_w,  w + 4*nw, nw);
    k_f2bf<<<nw/1024, 256>>>(rp3_w,  w + 5*nw, nw);

    dim3 blk(256);
    dim3 gP(NC/128, (NB*NT)/128, 1);     // (4,128,1)
    dim3 gA(NT/128, NT/128, NB);         // (16,16,8)
    dim3 gF(NC/128, NT/128, NB);         // (4,16,8)
    dim3 gTv(NC/64, NT/64, NB);          // V transpose
    dim3 gTe(NT/64, NT/64, NB);          // E transpose
    const int dwBlocks = (NX/2)/256;

    // projections -> Q_l, Q_r, V_lT, V_rT
    k_gemm_nt<1><<<gP, blk>>>(xbl, w + 0*nw, H, NB*NT, NC, NC, 0,0,0, lp1_b1, nullptr,0, nullptr, 0.f);
    k_dw<<<dwBlocks, 256>>>(H, lp1_w2, lp1_b2, Ql);
    k_gemm_nt<1><<<gP, blk>>>(xbr, w + 1*nw, H, NB*NT, NC, NC, 0,0,0, rp1_b1, nullptr,0, nullptr, 0.f);
    k_dw<<<dwBlocks, 256>>>(H, rp1_w2, rp1_b2, Qr);
    k_gemm_nt<1><<<gP, blk>>>(xbl, w + 2*nw, H, NB*NT, NC, NC, 0,0,0, lp2_b1, nullptr,0, nullptr, 0.f);
    k_dw<<<dwBlocks, 256>>>(H, lp2_w2, lp2_b2, Vt);
    k_transpose<<<gTv, 256>>>(Vt, VlT, NT, NC);
    k_gemm_nt<1><<<gP, blk>>>(xbr, w + 3*nw, H, NB*NT, NC, NC, 0,0,0, rp2_b1, nullptr,0, nullptr, 0.f);
    k_dw<<<dwBlocks, 256>>>(H, rp2_w2, rp2_b2, Vt);
    k_transpose<<<gTv, 256>>>(Vt, VrT, NT, NC);

    // scores -> unnormalized softmax numerators E = exp(scale * Q_l Q_r^T)
    k_gemm_nt<2><<<gA, blk>>>(Ql, Qr, E, NT, NT, NC,
                              (long long)NT*NC, (long long)NT*NC, (long long)NT*NT,
                              nullptr, nullptr, 0, nullptr, scale);

    // softmax denominators for both directions
    k_rowsum_inv<<<NB*NT, 256>>>(E, rinv, NT);
    k_transpose<<<gTe, 256>>>(E, ET, NT, NT);
    k_rowsum_inv<<<NB*NT, 256>>>(ET, cinv, NT);

    // attention applies (normalization folded into epilogue)
    k_gemm_nt<3><<<gF, blk>>>(E, VrT, F1, NT, NC, NT,
                              (long long)NT*NT, (long long)NC*NT, (long long)NT*NC,
                              nullptr, rinv, NT, nullptr, 0.f);
    k_gemm_nt<3><<<gF, blk>>>(ET, VlT, F2, NT, NC, NT,
                              (long long)NT*NT, (long long)NC*NT, (long long)NT*NC,
                              nullptr, cinv, NT, nullptr, 0.f);

    // output projections + residual -> fp32 out (out_l then out_r)
    float* out = (float*)d_out;
    k_gemm_nt<4><<<gP, blk>>>(F1, w + 4*nw, out,      NB*NT, NC, NC, 0,0,0, lp3_b, nullptr,0, x_l, 0.f);
    k_gemm_nt<4><<<gP, blk>>>(F2, w + 5*nw, out + nx, NB*NT, NC, NC, 0,0,0, rp3_b, nullptr,0, x_r, 0.f);
}